// round 1
// baseline (speedup 1.0000x reference)
#include <cuda_runtime.h>
#include <math.h>

// DistanceTransformLoss: BCE-with-logits mean + sqrt(border) where
// border = sum(pred_bin * dist) / count_nonzero, dist = vertical two-pass
// min-plus distance transform of targets along H.
//
// Shapes: predictions/targets (32, 1, 1024, 1024) float32. Output: 1 float.

#define N_IMG 32
#define HH 1024
#define WW 1024
#define NELEM (32ull * 1024ull * 1024ull)

// Global accumulators (graph-replay safe: re-zeroed by init kernel each launch)
__device__ double g_bce;
__device__ double g_total;
__device__ unsigned long long g_count;

__global__ void dtl_init_kernel() {
    g_bce = 0.0;
    g_total = 0.0;
    g_count = 0ull;
}

// Block = 1024 threads = 32 warps. Block handles 32 consecutive columns of one
// image, full H=1024. lane -> column offset (coalesced 128B per warp access),
// warp -> 32-row segment. Entire column scan lives in registers; cross-warp
// carries via one 32x32 smem tile using min-plus segment composition:
//   segment effect: c_out = min(A, c_in + 32)
//   carry into warp w (fwd): min_{v<w} (A_v + 32*(w-1-v))
//   element apply:           d[j] = min(f[j], carry + (j+1))
__global__ __launch_bounds__(1024, 1)
void dtl_main_kernel(const float* __restrict__ pred,
                     const float* __restrict__ tgt) {
    __shared__ float sA[32][32];
    __shared__ double sBce[32];
    __shared__ double sTot[32];
    __shared__ unsigned long long sCnt[32];

    const int lane = threadIdx.x & 31;
    const int w    = threadIdx.x >> 5;
    const int n     = blockIdx.x >> 5;          // image index (32 blocks/image)
    const int cbase = (blockIdx.x & 31) << 5;   // column group base
    const int col   = cbase + lane;

    const size_t base = (size_t)n * HH * WW + (size_t)(w << 5) * WW + col;

    // ---- Load targets, pack to bitmask, local forward min-plus scan ----
    const float* tp = tgt + base;
    unsigned mask = 0u;
    float f[32];
    float carry = 1e30f;  // "inf"
    #pragma unroll
    for (int j = 0; j < 32; j++) {
        float t = tp[(size_t)j * WW];
        unsigned one = (t == 1.0f) ? 1u : 0u;
        mask |= one << j;
        float init = one ? 0.0f : (float)HH;
        carry = fminf(init, carry + 1.0f);
        f[j] = carry;
    }

    // ---- Forward cross-warp carry ----
    sA[w][lane] = f[31];
    __syncthreads();
    float cin = 1e30f;
    #pragma unroll
    for (int v = 0; v < 32; v++) {
        float cand = sA[v][lane] + 32.0f * (float)(w - 1 - v);
        if (v < w) cin = fminf(cin, cand);
    }
    #pragma unroll
    for (int j = 0; j < 32; j++)
        f[j] = fminf(f[j], cin + (float)(j + 1));
    __syncthreads();  // before smem reuse

    // ---- Local backward min-plus scan (in place, on Dfwd) ----
    #pragma unroll
    for (int j = 30; j >= 0; j--)
        f[j] = fminf(f[j], f[j + 1] + 1.0f);

    // ---- Backward cross-warp carry ----
    sA[w][lane] = f[0];
    __syncthreads();
    float cinb = 1e30f;
    #pragma unroll
    for (int v = 0; v < 32; v++) {
        float cand = sA[v][lane] + 32.0f * (float)(v - 1 - w);
        if (v > w) cinb = fminf(cinb, cand);
    }
    #pragma unroll
    for (int j = 0; j < 32; j++)
        f[j] = fminf(f[j], cinb + (float)(32 - j));

    // ---- Predictions pass: BCE + border penalty ----
    const float* pp = pred + base;
    float bce = 0.0f;
    float tot = 0.0f;
    int cnt = 0;
    #pragma unroll
    for (int j = 0; j < 32; j++) {
        float p = pp[(size_t)j * WW];
        float t = (float)((mask >> j) & 1u);
        float ax = fabsf(p);
        bce += fmaxf(p, 0.0f) - p * t + log1pf(__expf(-ax));
        if (p > 0.0f) {                 // sigmoid(p) > 0.5  <=>  p > 0
            float d = f[j];
            tot += d;
            cnt += (d != 0.0f) ? 1 : 0;
        }
    }

    // ---- Reduce: warp shfl -> smem -> warp0 shfl -> global double atomics ----
    #pragma unroll
    for (int o = 16; o > 0; o >>= 1) {
        bce += __shfl_xor_sync(0xffffffffu, bce, o);
        tot += __shfl_xor_sync(0xffffffffu, tot, o);
        cnt += __shfl_xor_sync(0xffffffffu, cnt, o);
    }
    if (lane == 0) {
        sBce[w] = (double)bce;
        sTot[w] = (double)tot;
        sCnt[w] = (unsigned long long)cnt;
    }
    __syncthreads();
    if (w == 0) {
        double b = sBce[lane];
        double tt = sTot[lane];
        unsigned long long c = sCnt[lane];
        #pragma unroll
        for (int o = 16; o > 0; o >>= 1) {
            b  += __shfl_xor_sync(0xffffffffu, b, o);
            tt += __shfl_xor_sync(0xffffffffu, tt, o);
            c  += __shfl_xor_sync(0xffffffffu, c, o);
        }
        if (lane == 0) {
            atomicAdd(&g_bce, b);
            atomicAdd(&g_total, tt);
            atomicAdd(&g_count, c);
        }
    }
}

__global__ void dtl_final_kernel(float* __restrict__ out) {
    double bce_mean = g_bce / (double)NELEM;
    double total = g_total;
    double cnt = (double)g_count;
    double border = (total == 0.0) ? 0.0 : total / fmax(cnt, 1.0);
    out[0] = (float)(bce_mean + sqrt(border));
}

extern "C" void kernel_launch(void* const* d_in, const int* in_sizes, int n_in,
                              void* d_out, int out_size) {
    const float* pred = (const float*)d_in[0];
    const float* tgt  = (const float*)d_in[1];
    float* out = (float*)d_out;

    dtl_init_kernel<<<1, 1>>>();
    // 32768 columns total / 32 columns per block = 1024 blocks
    dtl_main_kernel<<<1024, 1024>>>(pred, tgt);
    dtl_final_kernel<<<1, 1>>>(out);
}

// round 2
// speedup vs baseline: 1.2857x; 1.2857x over previous
#include <cuda_runtime.h>
#include <math.h>

// DistanceTransformLoss: BCE-with-logits mean + sqrt(border) where
// border = sum(pred_bin * dist) / count_nonzero and
// dist[i] = min(H, |i - nearest target row in column|)   (exact identity of
// the two-pass grassfire transform with init=H).
//
// Shapes: predictions/targets (32, 1, 1024, 1024) float32. Output: 1 float.

#define HH 1024
#define WW 1024
#define NELEM (32ull * 1024ull * 1024ull)
#define DINF (1 << 20)

// Accumulators. Zero-initialized at module load; the final kernel resets them
// after reading, so every kernel_launch invocation (and graph replay) starts
// from zero. Deterministic.
__device__ double g_bce;
__device__ double g_total;
__device__ unsigned long long g_count;

// Block = 1024 threads = 32 warps; covers 32 consecutive columns x full
// H=1024 of one image. lane -> column (coalesced 128B warp loads),
// warp -> 32-row chunk. Targets pack to a 32-bit mask per thread; distances
// are recomputed per element from the mask + integer cross-warp carries, so
// almost nothing stays live across phases (no spills, deep load batching).
__global__ __launch_bounds__(1024, 1)
void dtl_main_kernel(const float* __restrict__ pred,
                     const float* __restrict__ tgt) {
    __shared__ int sA[32][32];   // per-warp: dist from chunk bottom boundary up to last 1
    __shared__ int sB[32][32];   // per-warp: dist from chunk top boundary down to first 1
    __shared__ double sBce[32];
    __shared__ double sTot[32];
    __shared__ unsigned long long sCnt[32];

    const int lane = threadIdx.x & 31;
    const int w    = threadIdx.x >> 5;
    const int n     = blockIdx.x >> 5;          // image (32 blocks/image)
    const int cbase = (blockIdx.x & 31) << 5;   // column group base
    const int col   = cbase + lane;

    const size_t base = (size_t)n * HH * WW + (size_t)(w << 5) * WW + col;

    // ---- Load targets, pack mask (loads independent -> deep MLP) ----
    const float* tp = tgt + base;
    unsigned m = 0u;
    #pragma unroll
    for (int j = 0; j < 32; j++) {
        float t = __ldcs(tp + (size_t)j * WW);
        m |= (t == 1.0f ? 1u : 0u) << j;
    }

    // ---- Cross-warp carries (integer min-plus over chunk summaries) ----
    // A = distance from this chunk's row 32 (next chunk row 0) up to its last 1
    // B = distance from this chunk's row -1 (prev chunk row 31) down to its first 1
    sA[w][lane] = m ? (__clz(m) + 1) : DINF;   // 32 - msb(m)
    sB[w][lane] = m ? __ffs(m)       : DINF;   // (ffs-1) + 1
    __syncthreads();

    int U = DINF;   // dist from this chunk's row 0 to nearest 1 above
    #pragma unroll
    for (int v = 0; v < 32; v++)
        if (v < w) U = min(U, sA[v][lane] + 32 * (w - 1 - v));

    int Dn = DINF;  // dist from this chunk's row 31 to nearest 1 below
    #pragma unroll
    for (int v = 31; v >= 0; v--)
        if (v > w) Dn = min(Dn, sB[v][lane] + 32 * (v - 1 - w));

    // ---- Predictions pass: BCE + border penalty (dist from mask on the fly) ----
    const float* pp = pred + base;
    float bce = 0.0f;
    float tot = 0.0f;
    int cnt = 0;
    #pragma unroll
    for (int j = 0; j < 32; j++) {
        float p = __ldcs(pp + (size_t)j * WW);
        float t = (float)((m >> j) & 1u);
        float ax = fabsf(p);
        bce += fmaxf(p, 0.0f) - p * t + __logf(1.0f + __expf(-ax));

        unsigned mlow  = m << (31 - j);
        unsigned mhigh = m >> j;
        int dup   = mlow  ? __clz(mlow)      : U + j;
        int ddown = mhigh ? (__ffs(mhigh)-1) : Dn + (31 - j);
        int d = min(min(dup, ddown), HH);
        if (p > 0.0f) {             // sigmoid(p) > 0.5  <=>  p > 0
            tot += (float)d;
            cnt += (d != 0) ? 1 : 0;
        }
    }

    // ---- Reduce: warp shfl -> smem -> warp0 shfl -> global double atomics ----
    #pragma unroll
    for (int o = 16; o > 0; o >>= 1) {
        bce += __shfl_xor_sync(0xffffffffu, bce, o);
        tot += __shfl_xor_sync(0xffffffffu, tot, o);
        cnt += __shfl_xor_sync(0xffffffffu, cnt, o);
    }
    if (lane == 0) {
        sBce[w] = (double)bce;
        sTot[w] = (double)tot;
        sCnt[w] = (unsigned long long)cnt;
    }
    __syncthreads();
    if (w == 0) {
        double b  = sBce[lane];
        double tt = sTot[lane];
        unsigned long long c = sCnt[lane];
        #pragma unroll
        for (int o = 16; o > 0; o >>= 1) {
            b  += __shfl_xor_sync(0xffffffffu, b, o);
            tt += __shfl_xor_sync(0xffffffffu, tt, o);
            c  += __shfl_xor_sync(0xffffffffu, c, o);
        }
        if (lane == 0) {
            atomicAdd(&g_bce, b);
            atomicAdd(&g_total, tt);
            atomicAdd(&g_count, c);
        }
    }
}

__global__ void dtl_final_kernel(float* __restrict__ out) {
    double bce_mean = g_bce / (double)NELEM;
    double total = g_total;
    double cnt = (double)g_count;
    double border = (total == 0.0) ? 0.0 : total / fmax(cnt, 1.0);
    out[0] = (float)(bce_mean + sqrt(border));
    // Reset for next invocation / graph replay (entry invariant: all zero).
    g_bce = 0.0;
    g_total = 0.0;
    g_count = 0ull;
}

extern "C" void kernel_launch(void* const* d_in, const int* in_sizes, int n_in,
                              void* d_out, int out_size) {
    const float* pred = (const float*)d_in[0];
    const float* tgt  = (const float*)d_in[1];
    float* out = (float*)d_out;

    // 32768 columns total / 32 columns per block = 1024 blocks
    dtl_main_kernel<<<1024, 1024>>>(pred, tgt);
    dtl_final_kernel<<<1, 1>>>(out);
}